// round 10
// baseline (speedup 1.0000x reference)
#include <cuda_runtime.h>
#include <cstdint>

// Problem constants
#define RR 4
#define ND 81
#define NB 4
#define NC 128
#define NH 96
#define NW 160

// Tiling (R4 geometry)
#define TX 32
#define YB 4
#define PX 4
#define XG 8
#define NDY 9
#define NTHREADS 288
#define CCHUNK 8
#define NCHUNK 16
#define TGT_W 40
#define TGT_H 12
#define TGT_TILE (CCHUNK*TGT_H*TGT_W)    // 3840 floats
#define SRC_TILE (CCHUNK*YB*TX)          // 1024 floats
#define BUF_FLOATS (TGT_TILE + SRC_TILE) // 4864
#define BUF_BYTES (BUF_FLOATS*4)         // 19456
#define SMEM_BYTES (3*BUF_BYTES)         // 58368
#define NQUADS (BUF_FLOATS/4)            // 1216
#define MAXSLOTS 5
#define CBYTES (CCHUNK*NH*NW*4)

// Schedule: k1 = tiles 0..443 (one perfect wave: 148 SMs x 3 blocks).
// k2 = tiles 444..479 (36 tiles), each split 2-ways by channel -> 72 blocks,
// combined via exactly-2-way atomicAdd (commutative => bitwise deterministic).
#define K1_TILES 444
#define K2_TILES 36
#define NCHUNK2 8            // 64 channels per k2 block

// Leftover region (tiles 444..479): b=3, y in [64,96), all d, all x.
#define ZERO_QUADS (ND*32*(NW/4))   // 81*32*40 = 103680 float4s

__device__ __forceinline__ int disp_index(int dyv, int dxv) {
    int ay = dyv < 0 ? -dyv : dyv;
    int ax = dxv < 0 ? -dxv : dxv;
    if ((ay | ax) == 0) return 0;
    if (ax == 0) return 1 + (ay - 1) * 20 + (dyv < 0 ? 0 : 1);
    if (ay == 0) return 1 + (ax - 1) * 20 + (dxv < 0 ? 2 : 3);
    int base = 1 + (ay - 1) * 20 + 4 + (ax - 1) * 4;
    if (dyv < 0 && dxv < 0) return base + 0;
    if (dyv > 0 && dxv > 0) return base + 1;
    if (dyv < 0 && dxv > 0) return base + 2;
    return base + 3;
}

__device__ __forceinline__ void cp_async16(uint32_t saddr, const void* gaddr, int sz) {
    asm volatile("cp.async.cg.shared.global [%0], [%1], 16, %2;\n"
                 :: "r"(saddr), "l"(gaddr), "r"(sz));
}
__device__ __forceinline__ void cp_commit() {
    asm volatile("cp.async.commit_group;\n" ::: "memory");
}

// ---- zero the leftover-tile output region (it gets atomicAdd'ed) ----
__global__ void zero_leftover(float* __restrict__ out) {
    int q = blockIdx.x * blockDim.x + threadIdx.x;
    if (q >= ZERO_QUADS) return;
    int x4 = q % (NW / 4);
    int t  = q / (NW / 4);
    int y  = 64 + (t % 32);
    int d  = t / 32;
    float4* p = (float4*)(out + (((size_t)(3 * ND + d) * NH) + y) * NW) + x4;
    *p = make_float4(0.f, 0.f, 0.f, 0.f);
}

// ===================== Kernel 1: 444 uniform tiles =====================
__global__ __launch_bounds__(NTHREADS, 3)
void costvol_k1(const float* __restrict__ src,
                const float* __restrict__ tgt,
                float* __restrict__ out) {
    extern __shared__ __align__(16) float sm[];

    const int tid  = threadIdx.x;
    const int tile = blockIdx.x;           // 0..443
    const int b    = tile / 120;
    const int rem  = tile % 120;
    const int by   = rem / 5;
    const int bx   = rem % 5;
    const int x0   = bx * TX;
    const int y0   = by * YB;

    const char* srcB = (const char*)(src + (size_t)b * NC * NH * NW);
    const char* tgtB = (const char*)(tgt + (size_t)b * NC * NH * NW);

    uint32_t goff[MAXSLOTS];
    uint32_t flags = 0;
#pragma unroll
    for (int k = 0; k < MAXSLOTS; k++) {
        int idx = tid + k * NTHREADS;
        goff[k] = 0;
        if (idx < NQUADS) {
            if (idx < TGT_TILE / 4) {
                int cc  = idx / (TGT_H * (TGT_W / 4));
                int rm  = idx % (TGT_H * (TGT_W / 4));
                int row = rm / (TGT_W / 4);
                int xq  = rm % (TGT_W / 4);
                int gy = y0 + row - RR;
                int gx = x0 + xq * 4 - RR;
                bool ok = ((unsigned)gy < NH) && ((unsigned)gx < NW);
                if (ok) goff[k] = (uint32_t)(((cc * NH + gy) * NW + gx) * 4);
                flags |= 1u << k;
                if (ok) flags |= 1u << (k + 8);
            } else {
                int q   = idx - TGT_TILE / 4;
                int cc  = q / (YB * TX / 4);
                int rm  = q % (YB * TX / 4);
                int ry  = rm / (TX / 4);
                int xq  = rm % (TX / 4);
                goff[k] = (uint32_t)(((cc * NH + y0 + ry) * NW + x0 + xq * 4) * 4);
                flags |= 1u << (k + 8);
            }
        }
    }

    const uint32_t smem_base = (uint32_t)__cvta_generic_to_shared(&sm[0]);

    const int xg   = tid & (XG - 1);
    const int dyi  = (tid >> 3) % NDY;
    const int yr   = tid / (XG * NDY);
    const int dyv  = dyi - RR;
    const int trow = yr + dyi;
    const int t_off = trow * TGT_W + xg * PX;
    const int s_off = TGT_TILE + yr * TX + xg * PX;

    float acc[NDY][PX];
#pragma unroll
    for (int i = 0; i < NDY; i++)
#pragma unroll
        for (int p = 0; p < PX; p++) acc[i][p] = 0.0f;

    auto stage = [&](int bi) {
        const uint32_t bofs = (uint32_t)bi * BUF_BYTES;
#pragma unroll
        for (int k = 0; k < MAXSLOTS; k++) {
            if (k < MAXSLOTS - 1 || tid < NQUADS - (MAXSLOTS - 1) * NTHREADS) {
                const char* base = (flags >> k & 1) ? tgtB : srcB;
                int sz = (flags >> (k + 8) & 1) ? 16 : 0;
                cp_async16(smem_base + bofs + (uint32_t)(tid + k * NTHREADS) * 16,
                           base + goff[k], sz);
                goff[k] += CBYTES;
            }
        }
        cp_commit();
    };

    stage(0);
    stage(1);

#pragma unroll 1
    for (int ch = 0; ch < NCHUNK; ch++) {
        if (ch + 2 < NCHUNK)
            asm volatile("cp.async.wait_group 1;\n" ::: "memory");
        else
            asm volatile("cp.async.wait_group 0;\n" ::: "memory");
        __syncthreads();

        const float* bp = sm + (ch % 3) * BUF_FLOATS;
        const float* tb = bp + t_off;
        const float* sb = bp + s_off;
#pragma unroll
        for (int cc = 0; cc < CCHUNK; cc++) {
            float4 s4 = *(const float4*)(sb + cc * (YB * TX));
            const float4* tq = (const float4*)(tb + cc * (TGT_H * TGT_W));
            float4 t0 = tq[0], t1 = tq[1], t2 = tq[2];
            float s[PX] = {s4.x, s4.y, s4.z, s4.w};
            float t[12] = {t0.x, t0.y, t0.z, t0.w,
                           t1.x, t1.y, t1.z, t1.w,
                           t2.x, t2.y, t2.z, t2.w};
#pragma unroll
            for (int dx = 0; dx < NDY; dx++)
#pragma unroll
                for (int p = 0; p < PX; p++)
                    acc[dx][p] = fmaf(s[p], t[dx + p], acc[dx][p]);
        }

        if (ch + 2 < NCHUNK)
            stage((ch + 2) % 3);
    }

    const float inv = 1.0f / 81.0f;
    const int y = y0 + yr;
#pragma unroll
    for (int dx = 0; dx < NDY; dx++) {
        int d = disp_index(dyv, dx - RR);
        float* o = out + ((((size_t)b * ND + d) * NH) + y) * NW + x0 + xg * PX;
        float4 v = make_float4(acc[dx][0] * inv, acc[dx][1] * inv,
                               acc[dx][2] * inv, acc[dx][3] * inv);
        *(float4*)o = v;
    }
}

// ====== Kernel 2: 36 leftover tiles, 2-way channel split, atomicAdd ======
__global__ __launch_bounds__(NTHREADS, 3)
void costvol_k2(const float* __restrict__ src,
                const float* __restrict__ tgt,
                float* __restrict__ out) {
    extern __shared__ __align__(16) float sm[];

    const int tid  = threadIdx.x;
    const int tile = K1_TILES + (blockIdx.x >> 1);   // 444..479
    const int half = blockIdx.x & 1;                 // channel half
    const int c0bytes = half * 64 * NH * NW * 4;

    const int b   = tile / 120;
    const int rem = tile % 120;
    const int by  = rem / 5;
    const int bx  = rem % 5;
    const int x0  = bx * TX;
    const int y0  = by * YB;

    const char* srcB = (const char*)(src + (size_t)b * NC * NH * NW) + c0bytes;
    const char* tgtB = (const char*)(tgt + (size_t)b * NC * NH * NW) + c0bytes;

    uint32_t goff[MAXSLOTS];
    uint32_t flags = 0;
#pragma unroll
    for (int k = 0; k < MAXSLOTS; k++) {
        int idx = tid + k * NTHREADS;
        goff[k] = 0;
        if (idx < NQUADS) {
            if (idx < TGT_TILE / 4) {
                int cc  = idx / (TGT_H * (TGT_W / 4));
                int rm  = idx % (TGT_H * (TGT_W / 4));
                int row = rm / (TGT_W / 4);
                int xq  = rm % (TGT_W / 4);
                int gy = y0 + row - RR;
                int gx = x0 + xq * 4 - RR;
                bool ok = ((unsigned)gy < NH) && ((unsigned)gx < NW);
                if (ok) goff[k] = (uint32_t)(((cc * NH + gy) * NW + gx) * 4);
                flags |= 1u << k;
                if (ok) flags |= 1u << (k + 8);
            } else {
                int q   = idx - TGT_TILE / 4;
                int cc  = q / (YB * TX / 4);
                int rm  = q % (YB * TX / 4);
                int ry  = rm / (TX / 4);
                int xq  = rm % (TX / 4);
                goff[k] = (uint32_t)(((cc * NH + y0 + ry) * NW + x0 + xq * 4) * 4);
                flags |= 1u << (k + 8);
            }
        }
    }

    const uint32_t smem_base = (uint32_t)__cvta_generic_to_shared(&sm[0]);

    const int xg   = tid & (XG - 1);
    const int dyi  = (tid >> 3) % NDY;
    const int yr   = tid / (XG * NDY);
    const int dyv  = dyi - RR;
    const int trow = yr + dyi;
    const int t_off = trow * TGT_W + xg * PX;
    const int s_off = TGT_TILE + yr * TX + xg * PX;

    float acc[NDY][PX];
#pragma unroll
    for (int i = 0; i < NDY; i++)
#pragma unroll
        for (int p = 0; p < PX; p++) acc[i][p] = 0.0f;

    auto stage = [&](int bi) {
        const uint32_t bofs = (uint32_t)bi * BUF_BYTES;
#pragma unroll
        for (int k = 0; k < MAXSLOTS; k++) {
            if (k < MAXSLOTS - 1 || tid < NQUADS - (MAXSLOTS - 1) * NTHREADS) {
                const char* base = (flags >> k & 1) ? tgtB : srcB;
                int sz = (flags >> (k + 8) & 1) ? 16 : 0;
                cp_async16(smem_base + bofs + (uint32_t)(tid + k * NTHREADS) * 16,
                           base + goff[k], sz);
                goff[k] += CBYTES;
            }
        }
        cp_commit();
    };

    stage(0);
    stage(1);

#pragma unroll 1
    for (int ch = 0; ch < NCHUNK2; ch++) {
        if (ch + 2 < NCHUNK2)
            asm volatile("cp.async.wait_group 1;\n" ::: "memory");
        else
            asm volatile("cp.async.wait_group 0;\n" ::: "memory");
        __syncthreads();

        const float* bp = sm + (ch % 3) * BUF_FLOATS;
        const float* tb = bp + t_off;
        const float* sb = bp + s_off;
#pragma unroll
        for (int cc = 0; cc < CCHUNK; cc++) {
            float4 s4 = *(const float4*)(sb + cc * (YB * TX));
            const float4* tq = (const float4*)(tb + cc * (TGT_H * TGT_W));
            float4 t0 = tq[0], t1 = tq[1], t2 = tq[2];
            float s[PX] = {s4.x, s4.y, s4.z, s4.w};
            float t[12] = {t0.x, t0.y, t0.z, t0.w,
                           t1.x, t1.y, t1.z, t1.w,
                           t2.x, t2.y, t2.z, t2.w};
#pragma unroll
            for (int dx = 0; dx < NDY; dx++)
#pragma unroll
                for (int p = 0; p < PX; p++)
                    acc[dx][p] = fmaf(s[p], t[dx + p], acc[dx][p]);
        }

        if (ch + 2 < NCHUNK2)
            stage((ch + 2) % 3);
    }

    // epilogue: exactly-2-way atomic accumulation (bitwise deterministic)
    const float inv = 1.0f / 81.0f;
    const int y = y0 + yr;
#pragma unroll
    for (int dx = 0; dx < NDY; dx++) {
        int d = disp_index(dyv, dx - RR);
        float* o = out + ((((size_t)b * ND + d) * NH) + y) * NW + x0 + xg * PX;
#pragma unroll
        for (int p = 0; p < PX; p++)
            atomicAdd(o + p, acc[dx][p] * inv);
    }
}

extern "C" void kernel_launch(void* const* d_in, const int* in_sizes, int n_in,
                              void* d_out, int out_size) {
    const float* src = (const float*)d_in[0];
    const float* tgt = (const float*)d_in[1];
    float* out = (float*)d_out;

    cudaFuncSetAttribute(costvol_k1,
                         cudaFuncAttributeMaxDynamicSharedMemorySize, SMEM_BYTES);
    cudaFuncSetAttribute(costvol_k2,
                         cudaFuncAttributeMaxDynamicSharedMemorySize, SMEM_BYTES);

    zero_leftover<<<(ZERO_QUADS + 255) / 256, 256>>>(out);
    costvol_k1<<<K1_TILES, NTHREADS, SMEM_BYTES>>>(src, tgt, out);
    costvol_k2<<<K2_TILES * 2, NTHREADS, SMEM_BYTES>>>(src, tgt, out);
}

// round 11
// speedup vs baseline: 1.0078x; 1.0078x over previous
#include <cuda_runtime.h>
#include <cstdint>

// Problem constants
#define RR 4
#define ND 81
#define NB 4
#define NC 128
#define NH 96
#define NW 160

// Full-tile geometry (proven R4/R9 core)
#define TX 32
#define YB 4
#define PX 4
#define XG 8
#define NDY 9
#define NTHREADS 288
#define CCHUNK 8
#define NCHUNK 16
#define TGT_W 40
#define TGT_H 12
#define TGT_TILE (CCHUNK*TGT_H*TGT_W)    // 3840 floats
#define SRC_TILE (CCHUNK*YB*TX)          // 1024 floats
#define BUF_FLOATS (TGT_TILE + SRC_TILE) // 4864
#define BUF_BYTES (BUF_FLOATS*4)         // 19456
#define SMEM_BYTES (3*BUF_BYTES)         // 58368
#define NQUADS (BUF_FLOATS/4)            // 1216
#define MAXSLOTS 5
#define CBYTES (CCHUNK*NH*NW*4)

// Half-tile (tail) geometry: 16 x 4 px, PX=2
#define TX2 16
#define TGT_W2 24
#define TGT2_TILE (CCHUNK*TGT_H*TGT_W2)   // 2304 floats
#define SRC2_TILE (CCHUNK*YB*TX2)         // 512 floats
#define BUF2_FLOATS (TGT2_TILE + SRC2_TILE) // 2816
#define BUF2_BYTES (BUF2_FLOATS*4)          // 11264
#define NQUADS2 (BUF2_FLOATS/4)             // 704 = 2*288 + 128

// Schedule: blocks 0..443 = full tiles (one perfect wave, 148 SMs x 3).
// Blocks 444..515 = 72 half-tiles covering leftover tiles 444..479.
#define K1_TILES 444
#define NBLOCKS 516

__device__ __forceinline__ int disp_index(int dyv, int dxv) {
    int ay = dyv < 0 ? -dyv : dyv;
    int ax = dxv < 0 ? -dxv : dxv;
    if ((ay | ax) == 0) return 0;
    if (ax == 0) return 1 + (ay - 1) * 20 + (dyv < 0 ? 0 : 1);
    if (ay == 0) return 1 + (ax - 1) * 20 + (dxv < 0 ? 2 : 3);
    int base = 1 + (ay - 1) * 20 + 4 + (ax - 1) * 4;
    if (dyv < 0 && dxv < 0) return base + 0;
    if (dyv > 0 && dxv > 0) return base + 1;
    if (dyv < 0 && dxv > 0) return base + 2;
    return base + 3;
}

__device__ __forceinline__ void cp_async16(uint32_t saddr, const void* gaddr, int sz) {
    asm volatile("cp.async.cg.shared.global [%0], [%1], 16, %2;\n"
                 :: "r"(saddr), "l"(gaddr), "r"(sz));
}
__device__ __forceinline__ void cp_commit() {
    asm volatile("cp.async.commit_group;\n" ::: "memory");
}

__global__ __launch_bounds__(NTHREADS, 3)
void costvol_kernel(const float* __restrict__ src,
                    const float* __restrict__ tgt,
                    float* __restrict__ out) {
    extern __shared__ __align__(16) float sm[];
    const int tid = threadIdx.x;
    const uint32_t smem_base = (uint32_t)__cvta_generic_to_shared(&sm[0]);

    if (blockIdx.x < K1_TILES) {
        // =================== FULL TILE PATH (444 blocks) ===================
        const int tile = blockIdx.x;
        const int b    = tile / 120;
        const int rem  = tile % 120;
        const int by   = rem / 5;
        const int bx   = rem % 5;
        const int x0   = bx * TX;
        const int y0   = by * YB;

        const char* srcB = (const char*)(src + (size_t)b * NC * NH * NW);
        const char* tgtB = (const char*)(tgt + (size_t)b * NC * NH * NW);

        uint32_t goff[MAXSLOTS];
        uint32_t flags = 0;
#pragma unroll
        for (int k = 0; k < MAXSLOTS; k++) {
            int idx = tid + k * NTHREADS;
            goff[k] = 0;
            if (idx < NQUADS) {
                if (idx < TGT_TILE / 4) {
                    int cc  = idx / (TGT_H * (TGT_W / 4));
                    int rm  = idx % (TGT_H * (TGT_W / 4));
                    int row = rm / (TGT_W / 4);
                    int xq  = rm % (TGT_W / 4);
                    int gy = y0 + row - RR;
                    int gx = x0 + xq * 4 - RR;
                    bool ok = ((unsigned)gy < NH) && ((unsigned)gx < NW);
                    if (ok) goff[k] = (uint32_t)(((cc * NH + gy) * NW + gx) * 4);
                    flags |= 1u << k;
                    if (ok) flags |= 1u << (k + 8);
                } else {
                    int q   = idx - TGT_TILE / 4;
                    int cc  = q / (YB * TX / 4);
                    int rm  = q % (YB * TX / 4);
                    int ry  = rm / (TX / 4);
                    int xq  = rm % (TX / 4);
                    goff[k] = (uint32_t)(((cc * NH + y0 + ry) * NW + x0 + xq * 4) * 4);
                    flags |= 1u << (k + 8);
                }
            }
        }

        const int xg   = tid & (XG - 1);
        const int dyi  = (tid >> 3) % NDY;
        const int yr   = tid / (XG * NDY);
        const int dyv  = dyi - RR;
        const int trow = yr + dyi;
        const int t_off = trow * TGT_W + xg * PX;
        const int s_off = TGT_TILE + yr * TX + xg * PX;

        float acc[NDY][PX];
#pragma unroll
        for (int i = 0; i < NDY; i++)
#pragma unroll
            for (int p = 0; p < PX; p++) acc[i][p] = 0.0f;

        auto stage = [&](int bi) {
            const uint32_t bofs = (uint32_t)bi * BUF_BYTES;
#pragma unroll
            for (int k = 0; k < MAXSLOTS; k++) {
                if (k < MAXSLOTS - 1 || tid < NQUADS - (MAXSLOTS - 1) * NTHREADS) {
                    const char* base = (flags >> k & 1) ? tgtB : srcB;
                    int sz = (flags >> (k + 8) & 1) ? 16 : 0;
                    cp_async16(smem_base + bofs + (uint32_t)(tid + k * NTHREADS) * 16,
                               base + goff[k], sz);
                    goff[k] += CBYTES;
                }
            }
            cp_commit();
        };

        stage(0);
        stage(1);

#pragma unroll 1
        for (int ch = 0; ch < NCHUNK; ch++) {
            if (ch + 2 < NCHUNK)
                asm volatile("cp.async.wait_group 1;\n" ::: "memory");
            else
                asm volatile("cp.async.wait_group 0;\n" ::: "memory");
            __syncthreads();

            const float* bp = sm + (ch % 3) * BUF_FLOATS;
            const float* tb = bp + t_off;
            const float* sb = bp + s_off;
#pragma unroll
            for (int cc = 0; cc < CCHUNK; cc++) {
                float4 s4 = *(const float4*)(sb + cc * (YB * TX));
                const float4* tq = (const float4*)(tb + cc * (TGT_H * TGT_W));
                float4 t0 = tq[0], t1 = tq[1], t2 = tq[2];
                float s[PX] = {s4.x, s4.y, s4.z, s4.w};
                float t[12] = {t0.x, t0.y, t0.z, t0.w,
                               t1.x, t1.y, t1.z, t1.w,
                               t2.x, t2.y, t2.z, t2.w};
#pragma unroll
                for (int dx = 0; dx < NDY; dx++)
#pragma unroll
                    for (int p = 0; p < PX; p++)
                        acc[dx][p] = fmaf(s[p], t[dx + p], acc[dx][p]);
            }

            if (ch + 2 < NCHUNK)
                stage((ch + 2) % 3);
        }

        const float inv = 1.0f / 81.0f;
        const int y = y0 + yr;
#pragma unroll
        for (int dx = 0; dx < NDY; dx++) {
            int d = disp_index(dyv, dx - RR);
            float* o = out + ((((size_t)b * ND + d) * NH) + y) * NW + x0 + xg * PX;
            float4 v = make_float4(acc[dx][0] * inv, acc[dx][1] * inv,
                                   acc[dx][2] * inv, acc[dx][3] * inv);
            *(float4*)o = v;
        }
    } else {
        // ============ HALF TILE PATH (72 blocks, 16x4 px, PX=2) ============
        const int hb   = blockIdx.x - K1_TILES;       // 0..71
        const int tile = K1_TILES + (hb >> 1);        // 444..479
        const int b    = tile / 120;                  // always 3
        const int rem  = tile % 120;
        const int by   = rem / 5;
        const int bx   = rem % 5;
        const int x0   = bx * TX + (hb & 1) * TX2;
        const int y0   = by * YB;

        const char* srcB = (const char*)(src + (size_t)b * NC * NH * NW);
        const char* tgtB = (const char*)(tgt + (size_t)b * NC * NH * NW);

        // staging: 704 quads = 576 tgt (8cc x 12row x 6xq) + 128 src
        uint32_t goff[3];
        uint32_t flags = 0;   // bit k: tgt; bit k+8: in-bounds
#pragma unroll
        for (int k = 0; k < 3; k++) {
            int idx = tid + k * NTHREADS;
            goff[k] = 0;
            if (idx < NQUADS2) {
                if (idx < TGT2_TILE / 4) {
                    int cc  = idx / (TGT_H * (TGT_W2 / 4));   // /72
                    int rm  = idx % (TGT_H * (TGT_W2 / 4));
                    int row = rm / (TGT_W2 / 4);              // /6
                    int xq  = rm % (TGT_W2 / 4);
                    int gy = y0 + row - RR;
                    int gx = x0 + xq * 4 - RR;
                    bool ok = ((unsigned)gy < NH) && ((unsigned)gx < NW);
                    if (ok) goff[k] = (uint32_t)(((cc * NH + gy) * NW + gx) * 4);
                    flags |= 1u << k;
                    if (ok) flags |= 1u << (k + 8);
                } else {
                    int q   = idx - TGT2_TILE / 4;
                    int cc  = q / (YB * TX2 / 4);             // /16
                    int rm  = q % (YB * TX2 / 4);
                    int ry  = rm / (TX2 / 4);
                    int xq  = rm % (TX2 / 4);
                    goff[k] = (uint32_t)(((cc * NH + y0 + ry) * NW + x0 + xq * 4) * 4);
                    flags |= 1u << (k + 8);
                }
            }
        }

        const int xg   = tid & (XG - 1);
        const int dyi  = (tid >> 3) % NDY;
        const int yr   = tid / (XG * NDY);
        const int dyv  = dyi - RR;
        const int trow = yr + dyi;
        const int t_off = trow * TGT_W2 + xg * 2;       // floats, 8B aligned
        const int s_off = TGT2_TILE + yr * TX2 + xg * 2;

        float acc[NDY][2];
#pragma unroll
        for (int i = 0; i < NDY; i++) { acc[i][0] = 0.0f; acc[i][1] = 0.0f; }

        auto stage2 = [&](int bi) {
            const uint32_t bofs = (uint32_t)bi * BUF2_BYTES;
#pragma unroll
            for (int k = 0; k < 3; k++) {
                if (k < 2 || tid < NQUADS2 - 2 * NTHREADS) {
                    const char* base = (flags >> k & 1) ? tgtB : srcB;
                    int sz = (flags >> (k + 8) & 1) ? 16 : 0;
                    cp_async16(smem_base + bofs + (uint32_t)(tid + k * NTHREADS) * 16,
                               base + goff[k], sz);
                    goff[k] += CBYTES;
                }
            }
            cp_commit();
        };

        stage2(0);
        stage2(1);

#pragma unroll 1
        for (int ch = 0; ch < NCHUNK; ch++) {
            if (ch + 2 < NCHUNK)
                asm volatile("cp.async.wait_group 1;\n" ::: "memory");
            else
                asm volatile("cp.async.wait_group 0;\n" ::: "memory");
            __syncthreads();

            const float* bp = sm + (ch % 3) * BUF2_FLOATS;
            const float* tb = bp + t_off;
            const float* sb = bp + s_off;
#pragma unroll
            for (int cc = 0; cc < CCHUNK; cc++) {
                float2 s2 = *(const float2*)(sb + cc * (YB * TX2));
                const float2* tq = (const float2*)(tb + cc * (TGT_H * TGT_W2));
                float t[10];
#pragma unroll
                for (int i = 0; i < 5; i++) {
                    float2 v = tq[i];
                    t[2 * i]     = v.x;
                    t[2 * i + 1] = v.y;
                }
#pragma unroll
                for (int dx = 0; dx < NDY; dx++) {
                    acc[dx][0] = fmaf(s2.x, t[dx],     acc[dx][0]);
                    acc[dx][1] = fmaf(s2.y, t[dx + 1], acc[dx][1]);
                }
            }

            if (ch + 2 < NCHUNK)
                stage2((ch + 2) % 3);
        }

        const float inv = 1.0f / 81.0f;
        const int y = y0 + yr;
#pragma unroll
        for (int dx = 0; dx < NDY; dx++) {
            int d = disp_index(dyv, dx - RR);
            float* o = out + ((((size_t)b * ND + d) * NH) + y) * NW + x0 + xg * 2;
            *(float2*)o = make_float2(acc[dx][0] * inv, acc[dx][1] * inv);
        }
    }
}

extern "C" void kernel_launch(void* const* d_in, const int* in_sizes, int n_in,
                              void* d_out, int out_size) {
    const float* src = (const float*)d_in[0];
    const float* tgt = (const float*)d_in[1];
    float* out = (float*)d_out;

    cudaFuncSetAttribute(costvol_kernel,
                         cudaFuncAttributeMaxDynamicSharedMemorySize, SMEM_BYTES);

    costvol_kernel<<<NBLOCKS, NTHREADS, SMEM_BYTES>>>(src, tgt, out);
}